// round 1
// baseline (speedup 1.0000x reference)
#include <cuda_runtime.h>

#define BB 2
#define NN 2048
#define EE 256
#define HH 4
#define DK 64
#define BM 128
#define BN 64

// scratch (no allocations allowed in kernel_launch)
__device__ float g_Q[BB*HH*NN*DK];
__device__ float g_K[BB*HH*NN*DK];
__device__ float g_V[BB*HH*NN*DK];
__device__ float g_Hc[BB*NN*EE];

// ---------------------------------------------------------------------------
// Kernel 1: QKV projection. grid = (M/64, 12) ; blockIdx.y -> (mat, head)
// out[b,h,n,e] = sum_d x[b,n,d] * W[h,d,e]
// ---------------------------------------------------------------------------
__global__ void qkv_proj_kernel(const float* __restrict__ x,
                                const float* __restrict__ Wq,
                                const float* __restrict__ Wk,
                                const float* __restrict__ Wv) {
    __shared__ float Xs[64][33];
    __shared__ float Ws[32][65];
    int mat = blockIdx.y >> 2;
    int h   = blockIdx.y & 3;
    const float* W  = (mat == 0) ? Wq : (mat == 1 ? Wk : Wv);
    float* outp     = (mat == 0) ? g_Q : (mat == 1 ? g_K : g_V);
    int m0  = blockIdx.x * 64;
    int tid = threadIdx.x;
    int tr = tid >> 4, tc = tid & 15;

    float acc[4][4] = {};
    for (int k0 = 0; k0 < EE; k0 += 32) {
        #pragma unroll
        for (int i = 0; i < 8; i++) {
            int r = (tid >> 5) + i * 8;
            int c = tid & 31;
            Xs[r][c] = x[(m0 + r) * EE + k0 + c];
        }
        #pragma unroll
        for (int i = 0; i < 8; i++) {
            int kk = (tid >> 6) + i * 4;
            int cc = tid & 63;
            Ws[kk][cc] = W[(h * EE + k0 + kk) * DK + cc];
        }
        __syncthreads();
        #pragma unroll
        for (int kk = 0; kk < 32; kk++) {
            float a[4], bv[4];
            #pragma unroll
            for (int i = 0; i < 4; i++) a[i] = Xs[tr * 4 + i][kk];
            #pragma unroll
            for (int j = 0; j < 4; j++) bv[j] = Ws[kk][tc * 4 + j];
            #pragma unroll
            for (int i = 0; i < 4; i++)
                #pragma unroll
                for (int j = 0; j < 4; j++)
                    acc[i][j] += a[i] * bv[j];
        }
        __syncthreads();
    }
    #pragma unroll
    for (int i = 0; i < 4; i++) {
        int m = m0 + tr * 4 + i;
        int b = m >> 11;
        int n = m & (NN - 1);
        float* dst = outp + ((size_t)(b * HH + h) * NN + n) * DK;
        #pragma unroll
        for (int j = 0; j < 4; j++) dst[tc * 4 + j] = acc[i][j];
    }
}

// ---------------------------------------------------------------------------
// Kernel 2: adjacency-masked flash attention.
// grid = (N/BM, B*H), 256 threads. Each thread: 8x4 microtile of S and O.
// ---------------------------------------------------------------------------
__global__ void flash_attn_kernel(const int* __restrict__ adj) {
    extern __shared__ float sm[];
    float* Qs     = sm;                 // 128*65
    float* Ks     = Qs + 128 * 65;      // 64*65
    float* Vs     = Ks + 64 * 65;       // 64*65
    float* Ss     = Vs + 64 * 65;       // 128*65
    float* m_s    = Ss + 128 * 65;      // 128
    float* l_s    = m_s + 128;          // 128
    float* corr_s = l_s + 128;          // 128
    int*   adjs   = (int*)(corr_s + 128); // 128*64

    int tid = threadIdx.x;
    int bh  = blockIdx.y;
    int b   = bh >> 2;
    int h   = bh & 3;
    int q0  = blockIdx.x * BM;
    const float scale = 0.125f; // 1/sqrt(64)

    const float* Qg = g_Q + ((size_t)bh * NN + q0) * DK;
    for (int idx = tid; idx < BM * DK; idx += 256) {
        int r = idx >> 6, c = idx & 63;
        Qs[r * 65 + c] = Qg[r * DK + c] * scale;
    }
    if (tid < BM) { m_s[tid] = -1e30f; l_s[tid] = 0.f; }

    int tr = tid >> 4, tc = tid & 15;   // tr in 0..15 (8 rows each), tc in 0..15 (4 cols)
    float o[8][4] = {};
    __syncthreads();

    for (int t = 0; t < NN / BN; t++) {
        int c0 = t * BN;
        const float* Kg = g_K + ((size_t)bh * NN + c0) * DK;
        const float* Vg = g_V + ((size_t)bh * NN + c0) * DK;
        for (int idx = tid; idx < BN * DK; idx += 256) {
            int r = idx >> 6, c = idx & 63;
            Ks[r * 65 + c] = Kg[r * DK + c];
            Vs[r * 65 + c] = Vg[r * DK + c];
        }
        const int* Ag = adj + ((size_t)b * NN + q0) * NN + c0;
        for (int idx = tid; idx < BM * BN; idx += 256) {
            int r = idx >> 6, c = idx & 63;
            adjs[idx] = Ag[(size_t)r * NN + c];
        }
        __syncthreads();

        // ---- S = Qs * Ks^T (8x4 per thread)
        float s[8][4] = {};
        #pragma unroll 8
        for (int e = 0; e < DK; e++) {
            float a[8], bv[4];
            #pragma unroll
            for (int i = 0; i < 8; i++) a[i] = Qs[(tr * 8 + i) * 65 + e];
            #pragma unroll
            for (int j = 0; j < 4; j++) bv[j] = Ks[(tc * 4 + j) * 65 + e];
            #pragma unroll
            for (int i = 0; i < 8; i++)
                #pragma unroll
                for (int j = 0; j < 4; j++)
                    s[i][j] += a[i] * bv[j];
        }
        // mask + stage to SMEM
        #pragma unroll
        for (int i = 0; i < 8; i++) {
            int r = tr * 8 + i;
            #pragma unroll
            for (int j = 0; j < 4; j++) {
                int c = tc * 4 + j;
                Ss[r * 65 + c] = adjs[r * 64 + c] ? s[i][j] : -1e30f;
            }
        }
        __syncthreads();

        // ---- online softmax: 2 threads per row
        {
            int row = tid >> 1, sub = tid & 1;
            float* Srow = Ss + row * 65 + sub * 32;
            float mloc = -1e30f;
            #pragma unroll
            for (int c = 0; c < 32; c++) mloc = fmaxf(mloc, Srow[c]);
            mloc = fmaxf(mloc, __shfl_xor_sync(0xffffffffu, mloc, 1));
            float mprev = m_s[row];
            float mnew  = fmaxf(mprev, mloc);
            float sum = 0.f;
            #pragma unroll
            for (int c = 0; c < 32; c++) {
                float p = __expf(Srow[c] - mnew);
                Srow[c] = p;
                sum += p;
            }
            sum += __shfl_xor_sync(0xffffffffu, sum, 1);
            if (sub == 0) {
                float cf = __expf(mprev - mnew);
                l_s[row]    = l_s[row] * cf + sum;
                m_s[row]    = mnew;
                corr_s[row] = cf;
            }
        }
        __syncthreads();

        // ---- rescale O then O += P * V
        float cf[8];
        #pragma unroll
        for (int i = 0; i < 8; i++) {
            cf[i] = corr_s[tr * 8 + i];
            #pragma unroll
            for (int j = 0; j < 4; j++) o[i][j] *= cf[i];
        }
        #pragma unroll 8
        for (int e = 0; e < BN; e++) {
            float p[8], v[4];
            #pragma unroll
            for (int i = 0; i < 8; i++) p[i] = Ss[(tr * 8 + i) * 65 + e];
            #pragma unroll
            for (int j = 0; j < 4; j++) v[j] = Vs[e * 65 + tc * 4 + j];
            #pragma unroll
            for (int i = 0; i < 8; i++)
                #pragma unroll
                for (int j = 0; j < 4; j++)
                    o[i][j] += p[i] * v[j];
        }
        __syncthreads();
    }

    // epilogue: normalize, write to concat buffer (b, n, h*DK + c)
    #pragma unroll
    for (int i = 0; i < 8; i++) {
        int r = tr * 8 + i;
        float inv = 1.f / l_s[r];
        float* dst = g_Hc + ((size_t)(b * NN) + q0 + r) * EE + h * DK;
        #pragma unroll
        for (int j = 0; j < 4; j++) dst[tc * 4 + j] = o[i][j] * inv;
    }
}

// ---------------------------------------------------------------------------
// Kernel 3: out = Hc @ Wo^T + bo.  grid = (M/64, E/64)
// ---------------------------------------------------------------------------
__global__ void out_proj_kernel(const float* __restrict__ Wo,
                                const float* __restrict__ bo,
                                float* __restrict__ out) {
    __shared__ float Xs[64][33];
    __shared__ float Ws[32][65];
    int m0 = blockIdx.x * 64;
    int c0 = blockIdx.y * 64;
    int tid = threadIdx.x;
    int tr = tid >> 4, tc = tid & 15;

    float acc[4][4] = {};
    for (int k0 = 0; k0 < EE; k0 += 32) {
        #pragma unroll
        for (int i = 0; i < 8; i++) {
            int r = (tid >> 5) + i * 8;
            int c = tid & 31;
            Xs[r][c] = g_Hc[(size_t)(m0 + r) * EE + k0 + c];
        }
        #pragma unroll
        for (int i = 0; i < 8; i++) {
            int cc = (tid >> 5) + i * 8;
            int kk = tid & 31;
            Ws[kk][cc] = Wo[(size_t)(c0 + cc) * EE + k0 + kk];
        }
        __syncthreads();
        #pragma unroll
        for (int kk = 0; kk < 32; kk++) {
            float a[4], bv[4];
            #pragma unroll
            for (int i = 0; i < 4; i++) a[i] = Xs[tr * 4 + i][kk];
            #pragma unroll
            for (int j = 0; j < 4; j++) bv[j] = Ws[kk][tc * 4 + j];
            #pragma unroll
            for (int i = 0; i < 4; i++)
                #pragma unroll
                for (int j = 0; j < 4; j++)
                    acc[i][j] += a[i] * bv[j];
        }
        __syncthreads();
    }
    #pragma unroll
    for (int i = 0; i < 4; i++) {
        int m = m0 + tr * 4 + i;
        #pragma unroll
        for (int j = 0; j < 4; j++) {
            int c = c0 + tc * 4 + j;
            out[(size_t)m * EE + c] = acc[i][j] + bo[c];
        }
    }
}

extern "C" void kernel_launch(void* const* d_in, const int* in_sizes, int n_in,
                              void* d_out, int out_size) {
    const float* x   = (const float*)d_in[0];
    const int*   adj = (const int*)  d_in[1];
    const float* Wq  = (const float*)d_in[2];
    const float* Wk  = (const float*)d_in[3];
    const float* Wv  = (const float*)d_in[4];
    const float* Wo  = (const float*)d_in[5];
    const float* bo  = (const float*)d_in[6];
    float* out = (float*)d_out;

    qkv_proj_kernel<<<dim3((BB * NN) / 64, 12), 256>>>(x, Wq, Wk, Wv);

    size_t smem = (size_t)(128 * 65 + 64 * 65 + 64 * 65 + 128 * 65 + 3 * 128) * 4
                + (size_t)128 * 64 * 4;
    cudaFuncSetAttribute(flash_attn_kernel,
                         cudaFuncAttributeMaxDynamicSharedMemorySize, (int)smem);
    flash_attn_kernel<<<dim3(NN / BM, BB * HH), 256, smem>>>(adj);

    out_proj_kernel<<<dim3((BB * NN) / 64, EE / 64), 256>>>(Wo, bo, out);
}

// round 3
// speedup vs baseline: 1.7395x; 1.7395x over previous
#include <cuda_runtime.h>
#include <cstdint>

#define BB 2
#define NN 2048
#define EE 256
#define HH 4
#define DK 64
#define QM 64      // q rows per CTA
#define BN 64      // keys per tile

// scratch (no allocations allowed anywhere)
__device__ float g_Q[BB*HH*NN*DK];
__device__ float g_K[BB*HH*NN*DK];
__device__ float g_V[BB*HH*NN*DK];
__device__ float g_Hc[BB*NN*EE];

__device__ __forceinline__ uint32_t to_tf32(float x) {
    uint32_t u;
    asm("cvt.rna.tf32.f32 %0, %1;" : "=r"(u) : "f"(x));
    return u;
}

__device__ __forceinline__ void mma_tf32(float* c, const uint32_t* a,
                                         uint32_t b0, uint32_t b1) {
    asm volatile(
        "mma.sync.aligned.m16n8k8.row.col.f32.tf32.tf32.f32 "
        "{%0,%1,%2,%3}, {%4,%5,%6,%7}, {%8,%9}, {%0,%1,%2,%3};\n"
        : "+f"(c[0]), "+f"(c[1]), "+f"(c[2]), "+f"(c[3])
        : "r"(a[0]), "r"(a[1]), "r"(a[2]), "r"(a[3]), "r"(b0), "r"(b1));
}

// ===========================================================================
// Kernel 1: QKV projection (unchanged)
// ===========================================================================
__global__ void qkv_proj_kernel(const float* __restrict__ x,
                                const float* __restrict__ Wq,
                                const float* __restrict__ Wk,
                                const float* __restrict__ Wv) {
    __shared__ float Xs[64][33];
    __shared__ float Ws[32][65];
    int mat = blockIdx.y >> 2;
    int h   = blockIdx.y & 3;
    const float* W  = (mat == 0) ? Wq : (mat == 1 ? Wk : Wv);
    float* outp     = (mat == 0) ? g_Q : (mat == 1 ? g_K : g_V);
    int m0  = blockIdx.x * 64;
    int tid = threadIdx.x;
    int tr = tid >> 4, tc = tid & 15;

    float acc[4][4] = {};
    for (int k0 = 0; k0 < EE; k0 += 32) {
        #pragma unroll
        for (int i = 0; i < 8; i++) {
            int r = (tid >> 5) + i * 8;
            int c = tid & 31;
            Xs[r][c] = x[(m0 + r) * EE + k0 + c];
        }
        #pragma unroll
        for (int i = 0; i < 8; i++) {
            int kk = (tid >> 6) + i * 4;
            int cc = tid & 63;
            Ws[kk][cc] = W[(h * EE + k0 + kk) * DK + cc];
        }
        __syncthreads();
        #pragma unroll
        for (int kk = 0; kk < 32; kk++) {
            float a[4], bv[4];
            #pragma unroll
            for (int i = 0; i < 4; i++) a[i] = Xs[tr * 4 + i][kk];
            #pragma unroll
            for (int j = 0; j < 4; j++) bv[j] = Ws[kk][tc * 4 + j];
            #pragma unroll
            for (int i = 0; i < 4; i++)
                #pragma unroll
                for (int j = 0; j < 4; j++)
                    acc[i][j] += a[i] * bv[j];
        }
        __syncthreads();
    }
    #pragma unroll
    for (int i = 0; i < 4; i++) {
        int m = m0 + tr * 4 + i;
        int b = m >> 11;
        int n = m & (NN - 1);
        float* dst = outp + ((size_t)(b * HH + h) * NN + n) * DK;
        #pragma unroll
        for (int j = 0; j < 4; j++) dst[tc * 4 + j] = acc[i][j];
    }
}

// ===========================================================================
// Kernel 2: flash attention with mma.sync tf32 (FA-2 style, register accum).
// grid = (N/64, B*H), 128 threads (4 warps x 16 q-rows).
// ===========================================================================
__global__ void __launch_bounds__(128) flash_mma_kernel(const int* __restrict__ adj) {
    __shared__ float Ks[BN][68];      // [key][d] tf32 bits as float
    __shared__ float Vs[BN][68];      // [key][d]
    __shared__ uint32_t adjm[QM][2];  // packed adjacency bits, [row][key/32]

    const int tid = threadIdx.x;
    const int wid = tid >> 5;
    const int lane = tid & 31;
    const int g = lane >> 2;          // groupID (row within warp-frag)
    const int t = lane & 3;           // thread in group (col quad)
    const int bh = blockIdx.y;
    const int b  = bh >> 2;
    const int h  = bh & 3;
    const int q0 = blockIdx.x * QM;

    const int row0 = wid * 16 + g;    // local q rows this thread owns
    const int row1 = row0 + 8;

    // --- preload Q fragments (scaled, tf32) ---
    uint32_t qa[8][4];
    {
        const float* Q0 = g_Q + ((size_t)bh * NN + q0 + row0) * DK;
        const float* Q1 = g_Q + ((size_t)bh * NN + q0 + row1) * DK;
        #pragma unroll
        for (int kc = 0; kc < 8; kc++) {
            qa[kc][0] = to_tf32(Q0[kc * 8 + t]     * 0.125f);
            qa[kc][1] = to_tf32(Q1[kc * 8 + t]     * 0.125f);
            qa[kc][2] = to_tf32(Q0[kc * 8 + t + 4] * 0.125f);
            qa[kc][3] = to_tf32(Q1[kc * 8 + t + 4] * 0.125f);
        }
    }

    float oacc[8][4] = {};
    float m0r = -1e30f, m1r = -1e30f, l0r = 0.f, l1r = 0.f;

    const int srow = tid >> 1;        // staging: row handled by this thread
    const int shalf = tid & 1;        // staging: which 32-col half

    for (int tile = 0; tile < NN / BN; tile++) {
        const int c0 = tile * BN;

        // ---- stage K, V (tf32-converted), adjacency bitmask ----
        {
            const float* Kg = g_K + ((size_t)bh * NN + c0 + srow) * DK + shalf * 32;
            const float* Vg = g_V + ((size_t)bh * NN + c0 + srow) * DK + shalf * 32;
            #pragma unroll
            for (int i = 0; i < 8; i++) {
                float4 kv = *(const float4*)(Kg + i * 4);
                float4 vv = *(const float4*)(Vg + i * 4);
                float4 kw, vw;
                kw.x = __uint_as_float(to_tf32(kv.x));
                kw.y = __uint_as_float(to_tf32(kv.y));
                kw.z = __uint_as_float(to_tf32(kv.z));
                kw.w = __uint_as_float(to_tf32(kv.w));
                vw.x = __uint_as_float(to_tf32(vv.x));
                vw.y = __uint_as_float(to_tf32(vv.y));
                vw.z = __uint_as_float(to_tf32(vv.z));
                vw.w = __uint_as_float(to_tf32(vv.w));
                *(float4*)(&Ks[srow][shalf * 32 + i * 4]) = kw;
                *(float4*)(&Vs[srow][shalf * 32 + i * 4]) = vw;
            }
            const int4* Ag = (const int4*)(adj + ((size_t)b * NN + q0 + srow) * NN + c0 + shalf * 32);
            uint32_t bits = 0;
            #pragma unroll
            for (int i = 0; i < 8; i++) {
                int4 a4 = Ag[i];
                bits |= (a4.x != 0 ? 1u : 0u) << (i * 4 + 0);
                bits |= (a4.y != 0 ? 1u : 0u) << (i * 4 + 1);
                bits |= (a4.z != 0 ? 1u : 0u) << (i * 4 + 2);
                bits |= (a4.w != 0 ? 1u : 0u) << (i * 4 + 3);
            }
            adjm[srow][shalf] = bits;
        }
        __syncthreads();

        // ---- S = Q K^T ----
        float sacc[8][4] = {};
        #pragma unroll
        for (int nf = 0; nf < 8; nf++) {
            #pragma unroll
            for (int kc = 0; kc < 8; kc++) {
                uint32_t b0 = __float_as_uint(Ks[nf * 8 + g][kc * 8 + t]);
                uint32_t b1 = __float_as_uint(Ks[nf * 8 + g][kc * 8 + t + 4]);
                mma_tf32(sacc[nf], qa[kc], b0, b1);
            }
        }

        // ---- masked online softmax on fragments ----
        uint32_t w0lo = adjm[row0][0], w0hi = adjm[row0][1];
        uint32_t w1lo = adjm[row1][0], w1hi = adjm[row1][1];
        float mx0 = -1e30f, mx1 = -1e30f;
        #pragma unroll
        for (int nf = 0; nf < 8; nf++) {
            int ca = nf * 8 + 2 * t, cb = ca + 1;
            uint32_t wr0 = (ca < 32) ? w0lo : w0hi;
            uint32_t wr1 = (ca < 32) ? w1lo : w1hi;
            int sa = ca & 31, sb = cb & 31;
            sacc[nf][0] = ((wr0 >> sa) & 1u) ? sacc[nf][0] : -1e38f;
            sacc[nf][1] = ((wr0 >> sb) & 1u) ? sacc[nf][1] : -1e38f;
            sacc[nf][2] = ((wr1 >> sa) & 1u) ? sacc[nf][2] : -1e38f;
            sacc[nf][3] = ((wr1 >> sb) & 1u) ? sacc[nf][3] : -1e38f;
            mx0 = fmaxf(mx0, fmaxf(sacc[nf][0], sacc[nf][1]));
            mx1 = fmaxf(mx1, fmaxf(sacc[nf][2], sacc[nf][3]));
        }
        mx0 = fmaxf(mx0, __shfl_xor_sync(0xffffffffu, mx0, 1));
        mx0 = fmaxf(mx0, __shfl_xor_sync(0xffffffffu, mx0, 2));
        mx1 = fmaxf(mx1, __shfl_xor_sync(0xffffffffu, mx1, 1));
        mx1 = fmaxf(mx1, __shfl_xor_sync(0xffffffffu, mx1, 2));
        float mn0 = fmaxf(m0r, mx0);
        float mn1 = fmaxf(m1r, mx1);
        float s0 = 0.f, s1 = 0.f;
        #pragma unroll
        for (int nf = 0; nf < 8; nf++) {
            float p0 = __expf(sacc[nf][0] - mn0);
            float p1 = __expf(sacc[nf][1] - mn0);
            float p2 = __expf(sacc[nf][2] - mn1);
            float p3 = __expf(sacc[nf][3] - mn1);
            s0 += p0 + p1;
            s1 += p2 + p3;
            sacc[nf][0] = __uint_as_float(to_tf32(p0));
            sacc[nf][1] = __uint_as_float(to_tf32(p1));
            sacc[nf][2] = __uint_as_float(to_tf32(p2));
            sacc[nf][3] = __uint_as_float(to_tf32(p3));
        }
        s0 += __shfl_xor_sync(0xffffffffu, s0, 1);
        s0 += __shfl_xor_sync(0xffffffffu, s0, 2);
        s1 += __shfl_xor_sync(0xffffffffu, s1, 1);
        s1 += __shfl_xor_sync(0xffffffffu, s1, 2);
        float cf0 = __expf(m0r - mn0);
        float cf1 = __expf(m1r - mn1);
        l0r = l0r * cf0 + s0;  m0r = mn0;
        l1r = l1r * cf1 + s1;  m1r = mn1;
        #pragma unroll
        for (int nf = 0; nf < 8; nf++) {
            oacc[nf][0] *= cf0; oacc[nf][1] *= cf0;
            oacc[nf][2] *= cf1; oacc[nf][3] *= cf1;
        }

        // ---- O += P V : convert P (C-layout) -> A-layout via quad shuffles ----
        const int src0 = (lane & ~3) | (t >> 1);
        const int src2 = src0 + 2;
        #pragma unroll
        for (int kc = 0; kc < 8; kc++) {
            float v00 = __shfl_sync(0xffffffffu, sacc[kc][0], src0);
            float v01 = __shfl_sync(0xffffffffu, sacc[kc][1], src0);
            float v10 = __shfl_sync(0xffffffffu, sacc[kc][2], src0);
            float v11 = __shfl_sync(0xffffffffu, sacc[kc][3], src0);
            float v20 = __shfl_sync(0xffffffffu, sacc[kc][0], src2);
            float v21 = __shfl_sync(0xffffffffu, sacc[kc][1], src2);
            float v30 = __shfl_sync(0xffffffffu, sacc[kc][2], src2);
            float v31 = __shfl_sync(0xffffffffu, sacc[kc][3], src2);
            uint32_t pa[4];
            pa[0] = __float_as_uint((t & 1) ? v01 : v00);
            pa[1] = __float_as_uint((t & 1) ? v11 : v10);
            pa[2] = __float_as_uint((t & 1) ? v21 : v20);
            pa[3] = __float_as_uint((t & 1) ? v31 : v30);
            #pragma unroll
            for (int nf = 0; nf < 8; nf++) {
                uint32_t b0 = __float_as_uint(Vs[kc * 8 + t][nf * 8 + g]);
                uint32_t b1 = __float_as_uint(Vs[kc * 8 + t + 4][nf * 8 + g]);
                mma_tf32(oacc[nf], pa, b0, b1);
            }
        }
        __syncthreads();
    }

    // ---- epilogue ----
    float inv0 = (l0r > 0.f) ? 1.f / l0r : 0.f;
    float inv1 = (l1r > 0.f) ? 1.f / l1r : 0.f;
    float* d0 = g_Hc + ((size_t)(b * NN + q0 + row0)) * EE + h * DK;
    float* d1 = g_Hc + ((size_t)(b * NN + q0 + row1)) * EE + h * DK;
    #pragma unroll
    for (int nf = 0; nf < 8; nf++) {
        int c = nf * 8 + 2 * t;
        float2 w0 = {oacc[nf][0] * inv0, oacc[nf][1] * inv0};
        float2 w1 = {oacc[nf][2] * inv1, oacc[nf][3] * inv1};
        *(float2*)(d0 + c) = w0;
        *(float2*)(d1 + c) = w1;
    }
}

// ===========================================================================
// Kernel 3: out = Hc @ Wo^T + bo (unchanged)
// ===========================================================================
__global__ void out_proj_kernel(const float* __restrict__ Wo,
                                const float* __restrict__ bo,
                                float* __restrict__ out) {
    __shared__ float Xs[64][33];
    __shared__ float Ws[32][65];
    int m0 = blockIdx.x * 64;
    int c0 = blockIdx.y * 64;
    int tid = threadIdx.x;
    int tr = tid >> 4, tc = tid & 15;

    float acc[4][4] = {};
    for (int k0 = 0; k0 < EE; k0 += 32) {
        #pragma unroll
        for (int i = 0; i < 8; i++) {
            int r = (tid >> 5) + i * 8;
            int c = tid & 31;
            Xs[r][c] = g_Hc[(size_t)(m0 + r) * EE + k0 + c];
        }
        #pragma unroll
        for (int i = 0; i < 8; i++) {
            int cc = (tid >> 5) + i * 8;
            int kk = tid & 31;
            Ws[kk][cc] = Wo[(size_t)(c0 + cc) * EE + k0 + kk];
        }
        __syncthreads();
        #pragma unroll
        for (int kk = 0; kk < 32; kk++) {
            float a[4], bv[4];
            #pragma unroll
            for (int i = 0; i < 4; i++) a[i] = Xs[tr * 4 + i][kk];
            #pragma unroll
            for (int j = 0; j < 4; j++) bv[j] = Ws[kk][tc * 4 + j];
            #pragma unroll
            for (int i = 0; i < 4; i++)
                #pragma unroll
                for (int j = 0; j < 4; j++)
                    acc[i][j] += a[i] * bv[j];
        }
        __syncthreads();
    }
    #pragma unroll
    for (int i = 0; i < 4; i++) {
        int m = m0 + tr * 4 + i;
        #pragma unroll
        for (int j = 0; j < 4; j++) {
            int c = c0 + tc * 4 + j;
            out[(size_t)m * EE + c] = acc[i][j] + bo[c];
        }
    }
}

extern "C" void kernel_launch(void* const* d_in, const int* in_sizes, int n_in,
                              void* d_out, int out_size) {
    const float* x   = (const float*)d_in[0];
    const int*   adj = (const int*)  d_in[1];
    const float* Wq  = (const float*)d_in[2];
    const float* Wk  = (const float*)d_in[3];
    const float* Wv  = (const float*)d_in[4];
    const float* Wo  = (const float*)d_in[5];
    const float* bo  = (const float*)d_in[6];
    float* out = (float*)d_out;

    qkv_proj_kernel<<<dim3((BB * NN) / 64, 12), 256>>>(x, Wq, Wk, Wv);
    flash_mma_kernel<<<dim3(NN / QM, BB * HH), 128>>>(adj);
    out_proj_kernel<<<dim3((BB * NN) / 64, EE / 64), 256>>>(Wo, bo, out);
}

// round 4
// speedup vs baseline: 2.0172x; 1.1596x over previous
#include <cuda_runtime.h>
#include <cstdint>

#define BB 2
#define NN 2048
#define EE 256
#define HH 4
#define DK 64
#define QM 128     // q rows per CTA (flash)
#define BN 64      // keys per tile (flash)

// scratch (no allocations allowed anywhere)
__device__ float g_Q[BB*HH*NN*DK];
__device__ float g_K[BB*HH*NN*DK];
__device__ float g_V[BB*HH*NN*DK];
__device__ float g_Hc[BB*NN*EE];

__device__ __forceinline__ uint32_t to_tf32(float x) {
    uint32_t u;
    asm("cvt.rna.tf32.f32 %0, %1;" : "=r"(u) : "f"(x));
    return u;
}

__device__ __forceinline__ void mma_tf32(float* c, const uint32_t* a,
                                         uint32_t b0, uint32_t b1) {
    asm volatile(
        "mma.sync.aligned.m16n8k8.row.col.f32.tf32.tf32.f32 "
        "{%0,%1,%2,%3}, {%4,%5,%6,%7}, {%8,%9}, {%0,%1,%2,%3};\n"
        : "+f"(c[0]), "+f"(c[1]), "+f"(c[2]), "+f"(c[3])
        : "r"(a[0]), "r"(a[1]), "r"(a[2]), "r"(a[3]), "r"(b0), "r"(b1));
}

__device__ __forceinline__ void hilo(float v, float& hi, float& lo) {
    uint32_t h = to_tf32(v);
    hi = __uint_as_float(h);
    lo = __uint_as_float(to_tf32(v - hi));
}

// ===========================================================================
// Kernel 1: QKV projection, 3xTF32 mma. grid = (64, 12), 128 threads.
// out[b,h,n,e] = sum_d x[b,n,d] * W[h,d,e]
// ===========================================================================
__global__ void __launch_bounds__(128) qkv_mma_kernel(const float* __restrict__ x,
                                                      const float* __restrict__ Wq,
                                                      const float* __restrict__ Wk,
                                                      const float* __restrict__ Wv) {
    __shared__ float Xhi[64][36], Xlo[64][36];
    __shared__ float Whi[32][72], Wlo[32][72];

    const int mat = blockIdx.y >> 2;
    const int h   = blockIdx.y & 3;
    const float* W  = (mat == 0) ? Wq : (mat == 1 ? Wk : Wv);
    float* outp     = (mat == 0) ? g_Q : (mat == 1 ? g_K : g_V);
    const int m0  = blockIdx.x * 64;
    const int tid = threadIdx.x;
    const int wid = tid >> 5;
    const int lane = tid & 31;
    const int g = lane >> 2, t = lane & 3;
    const int row0 = wid * 16 + g, row1 = row0 + 8;

    float c[8][4] = {};

    for (int k0 = 0; k0 < EE; k0 += 32) {
        {   // stage X chunk [64 rows x 32 k] hi/lo
            const int xr = tid >> 1, xq = tid & 1;
            const float* src = x + (size_t)(m0 + xr) * EE + k0 + xq * 16;
            #pragma unroll
            for (int i = 0; i < 4; i++) {
                float4 v = ((const float4*)src)[i];
                int cbase = xq * 16 + i * 4;
                hilo(v.x, Xhi[xr][cbase + 0], Xlo[xr][cbase + 0]);
                hilo(v.y, Xhi[xr][cbase + 1], Xlo[xr][cbase + 1]);
                hilo(v.z, Xhi[xr][cbase + 2], Xlo[xr][cbase + 2]);
                hilo(v.w, Xhi[xr][cbase + 3], Xlo[xr][cbase + 3]);
            }
        }
        {   // stage W chunk [32 k x 64 e] hi/lo
            const int kk = tid >> 2, wq = tid & 3;
            const float* src = W + (size_t)(h * EE + k0 + kk) * DK + wq * 16;
            #pragma unroll
            for (int i = 0; i < 4; i++) {
                float4 v = ((const float4*)src)[i];
                int cbase = wq * 16 + i * 4;
                hilo(v.x, Whi[kk][cbase + 0], Wlo[kk][cbase + 0]);
                hilo(v.y, Whi[kk][cbase + 1], Wlo[kk][cbase + 1]);
                hilo(v.z, Whi[kk][cbase + 2], Wlo[kk][cbase + 2]);
                hilo(v.w, Whi[kk][cbase + 3], Wlo[kk][cbase + 3]);
            }
        }
        __syncthreads();

        #pragma unroll
        for (int kc = 0; kc < 4; kc++) {
            uint32_t ahi[4], alo[4];
            ahi[0] = __float_as_uint(Xhi[row0][kc * 8 + t]);
            ahi[1] = __float_as_uint(Xhi[row1][kc * 8 + t]);
            ahi[2] = __float_as_uint(Xhi[row0][kc * 8 + t + 4]);
            ahi[3] = __float_as_uint(Xhi[row1][kc * 8 + t + 4]);
            alo[0] = __float_as_uint(Xlo[row0][kc * 8 + t]);
            alo[1] = __float_as_uint(Xlo[row1][kc * 8 + t]);
            alo[2] = __float_as_uint(Xlo[row0][kc * 8 + t + 4]);
            alo[3] = __float_as_uint(Xlo[row1][kc * 8 + t + 4]);
            #pragma unroll
            for (int nf = 0; nf < 8; nf++) {
                uint32_t bh0 = __float_as_uint(Whi[kc * 8 + t][nf * 8 + g]);
                uint32_t bh1 = __float_as_uint(Whi[kc * 8 + t + 4][nf * 8 + g]);
                uint32_t bl0 = __float_as_uint(Wlo[kc * 8 + t][nf * 8 + g]);
                uint32_t bl1 = __float_as_uint(Wlo[kc * 8 + t + 4][nf * 8 + g]);
                mma_tf32(c[nf], ahi, bh0, bh1);
                mma_tf32(c[nf], ahi, bl0, bl1);
                mma_tf32(c[nf], alo, bh0, bh1);
            }
        }
        __syncthreads();
    }

    // epilogue: write to (b,h,n,e) layout
    {
        int m = m0 + row0;
        int b = m >> 11, n = m & (NN - 1);
        float* dst = outp + ((size_t)(b * HH + h) * NN + n) * DK;
        #pragma unroll
        for (int nf = 0; nf < 8; nf++) {
            float2 w = {c[nf][0], c[nf][1]};
            *(float2*)(dst + nf * 8 + 2 * t) = w;
        }
    }
    {
        int m = m0 + row1;
        int b = m >> 11, n = m & (NN - 1);
        float* dst = outp + ((size_t)(b * HH + h) * NN + n) * DK;
        #pragma unroll
        for (int nf = 0; nf < 8; nf++) {
            float2 w = {c[nf][2], c[nf][3]};
            *(float2*)(dst + nf * 8 + 2 * t) = w;
        }
    }
}

// ===========================================================================
// Kernel 2: flash attention, mma.sync tf32, 8 warps / 128 q-rows per CTA.
// grid = (16, 8), 256 threads.
// ===========================================================================
__global__ void __launch_bounds__(256) flash_mma_kernel(const int* __restrict__ adj) {
    __shared__ float Ks[BN][68];
    __shared__ float Vs[BN][68];
    __shared__ uint32_t adjm[QM][2];

    const int tid = threadIdx.x;
    const int wid = tid >> 5;
    const int lane = tid & 31;
    const int g = lane >> 2;
    const int t = lane & 3;
    const int bh = blockIdx.y;
    const int b  = bh >> 2;
    const int h  = bh & 3;
    const int q0 = blockIdx.x * QM;

    const int row0 = wid * 16 + g;
    const int row1 = row0 + 8;

    // preload Q fragments (scaled, tf32)
    uint32_t qa[8][4];
    {
        const float* Q0 = g_Q + ((size_t)bh * NN + q0 + row0) * DK;
        const float* Q1 = g_Q + ((size_t)bh * NN + q0 + row1) * DK;
        #pragma unroll
        for (int kc = 0; kc < 8; kc++) {
            qa[kc][0] = to_tf32(Q0[kc * 8 + t]     * 0.125f);
            qa[kc][1] = to_tf32(Q1[kc * 8 + t]     * 0.125f);
            qa[kc][2] = to_tf32(Q0[kc * 8 + t + 4] * 0.125f);
            qa[kc][3] = to_tf32(Q1[kc * 8 + t + 4] * 0.125f);
        }
    }

    float oacc[8][4] = {};
    float m0r = -1e30f, m1r = -1e30f, l0r = 0.f, l1r = 0.f;

    const int krow = tid >> 2, kq = tid & 3;     // K/V staging: 4 float4 each
    const int arow = tid >> 1, ahalf = tid & 1;  // adj staging: 1 word each

    for (int tile = 0; tile < NN / BN; tile++) {
        const int c0 = tile * BN;

        // ---- stage K, V (tf32), adjacency bits ----
        {
            const float* Kg = g_K + ((size_t)bh * NN + c0 + krow) * DK + kq * 16;
            const float* Vg = g_V + ((size_t)bh * NN + c0 + krow) * DK + kq * 16;
            #pragma unroll
            for (int i = 0; i < 4; i++) {
                float4 kv = ((const float4*)Kg)[i];
                float4 vv = ((const float4*)Vg)[i];
                float4 kw, vw;
                kw.x = __uint_as_float(to_tf32(kv.x));
                kw.y = __uint_as_float(to_tf32(kv.y));
                kw.z = __uint_as_float(to_tf32(kv.z));
                kw.w = __uint_as_float(to_tf32(kv.w));
                vw.x = __uint_as_float(to_tf32(vv.x));
                vw.y = __uint_as_float(to_tf32(vv.y));
                vw.z = __uint_as_float(to_tf32(vv.z));
                vw.w = __uint_as_float(to_tf32(vv.w));
                *(float4*)(&Ks[krow][kq * 16 + i * 4]) = kw;
                *(float4*)(&Vs[krow][kq * 16 + i * 4]) = vw;
            }
            const int4* Ag = (const int4*)(adj + ((size_t)b * NN + q0 + arow) * NN + c0 + ahalf * 32);
            uint32_t bits = 0;
            #pragma unroll
            for (int i = 0; i < 8; i++) {
                int4 a4 = Ag[i];
                bits |= (a4.x != 0 ? 1u : 0u) << (i * 4 + 0);
                bits |= (a4.y != 0 ? 1u : 0u) << (i * 4 + 1);
                bits |= (a4.z != 0 ? 1u : 0u) << (i * 4 + 2);
                bits |= (a4.w != 0 ? 1u : 0u) << (i * 4 + 3);
            }
            adjm[arow][ahalf] = bits;
        }
        __syncthreads();

        // ---- S = Q K^T ----
        float sacc[8][4] = {};
        #pragma unroll
        for (int nf = 0; nf < 8; nf++) {
            #pragma unroll
            for (int kc = 0; kc < 8; kc++) {
                uint32_t b0 = __float_as_uint(Ks[nf * 8 + g][kc * 8 + t]);
                uint32_t b1 = __float_as_uint(Ks[nf * 8 + g][kc * 8 + t + 4]);
                mma_tf32(sacc[nf], qa[kc], b0, b1);
            }
        }

        // ---- masked online softmax ----
        uint32_t w0lo = adjm[row0][0], w0hi = adjm[row0][1];
        uint32_t w1lo = adjm[row1][0], w1hi = adjm[row1][1];
        float mx0 = -1e30f, mx1 = -1e30f;
        #pragma unroll
        for (int nf = 0; nf < 8; nf++) {
            int ca = nf * 8 + 2 * t, cb = ca + 1;
            uint32_t wr0 = (ca < 32) ? w0lo : w0hi;
            uint32_t wr1 = (ca < 32) ? w1lo : w1hi;
            int sa = ca & 31, sb = cb & 31;
            sacc[nf][0] = ((wr0 >> sa) & 1u) ? sacc[nf][0] : -1e38f;
            sacc[nf][1] = ((wr0 >> sb) & 1u) ? sacc[nf][1] : -1e38f;
            sacc[nf][2] = ((wr1 >> sa) & 1u) ? sacc[nf][2] : -1e38f;
            sacc[nf][3] = ((wr1 >> sb) & 1u) ? sacc[nf][3] : -1e38f;
            mx0 = fmaxf(mx0, fmaxf(sacc[nf][0], sacc[nf][1]));
            mx1 = fmaxf(mx1, fmaxf(sacc[nf][2], sacc[nf][3]));
        }
        mx0 = fmaxf(mx0, __shfl_xor_sync(0xffffffffu, mx0, 1));
        mx0 = fmaxf(mx0, __shfl_xor_sync(0xffffffffu, mx0, 2));
        mx1 = fmaxf(mx1, __shfl_xor_sync(0xffffffffu, mx1, 1));
        mx1 = fmaxf(mx1, __shfl_xor_sync(0xffffffffu, mx1, 2));
        float mn0 = fmaxf(m0r, mx0);
        float mn1 = fmaxf(m1r, mx1);
        float s0 = 0.f, s1 = 0.f;
        #pragma unroll
        for (int nf = 0; nf < 8; nf++) {
            float p0 = __expf(sacc[nf][0] - mn0);
            float p1 = __expf(sacc[nf][1] - mn0);
            float p2 = __expf(sacc[nf][2] - mn1);
            float p3 = __expf(sacc[nf][3] - mn1);
            s0 += p0 + p1;
            s1 += p2 + p3;
            sacc[nf][0] = __uint_as_float(to_tf32(p0));
            sacc[nf][1] = __uint_as_float(to_tf32(p1));
            sacc[nf][2] = __uint_as_float(to_tf32(p2));
            sacc[nf][3] = __uint_as_float(to_tf32(p3));
        }
        s0 += __shfl_xor_sync(0xffffffffu, s0, 1);
        s0 += __shfl_xor_sync(0xffffffffu, s0, 2);
        s1 += __shfl_xor_sync(0xffffffffu, s1, 1);
        s1 += __shfl_xor_sync(0xffffffffu, s1, 2);
        float cf0 = __expf(m0r - mn0);
        float cf1 = __expf(m1r - mn1);
        l0r = l0r * cf0 + s0;  m0r = mn0;
        l1r = l1r * cf1 + s1;  m1r = mn1;
        #pragma unroll
        for (int nf = 0; nf < 8; nf++) {
            oacc[nf][0] *= cf0; oacc[nf][1] *= cf0;
            oacc[nf][2] *= cf1; oacc[nf][3] *= cf1;
        }

        // ---- O += P V (P C-layout -> A-layout via quad shuffles) ----
        const int src0 = (lane & ~3) | (t >> 1);
        const int src2 = src0 + 2;
        #pragma unroll
        for (int kc = 0; kc < 8; kc++) {
            float v00 = __shfl_sync(0xffffffffu, sacc[kc][0], src0);
            float v01 = __shfl_sync(0xffffffffu, sacc[kc][1], src0);
            float v10 = __shfl_sync(0xffffffffu, sacc[kc][2], src0);
            float v11 = __shfl_sync(0xffffffffu, sacc[kc][3], src0);
            float v20 = __shfl_sync(0xffffffffu, sacc[kc][0], src2);
            float v21 = __shfl_sync(0xffffffffu, sacc[kc][1], src2);
            float v30 = __shfl_sync(0xffffffffu, sacc[kc][2], src2);
            float v31 = __shfl_sync(0xffffffffu, sacc[kc][3], src2);
            uint32_t pa[4];
            pa[0] = __float_as_uint((t & 1) ? v01 : v00);
            pa[1] = __float_as_uint((t & 1) ? v11 : v10);
            pa[2] = __float_as_uint((t & 1) ? v21 : v20);
            pa[3] = __float_as_uint((t & 1) ? v31 : v30);
            #pragma unroll
            for (int nf = 0; nf < 8; nf++) {
                uint32_t b0 = __float_as_uint(Vs[kc * 8 + t][nf * 8 + g]);
                uint32_t b1 = __float_as_uint(Vs[kc * 8 + t + 4][nf * 8 + g]);
                mma_tf32(oacc[nf], pa, b0, b1);
            }
        }
        __syncthreads();
    }

    // ---- epilogue ----
    float inv0 = (l0r > 0.f) ? 1.f / l0r : 0.f;
    float inv1 = (l1r > 0.f) ? 1.f / l1r : 0.f;
    float* d0 = g_Hc + ((size_t)(b * NN + q0 + row0)) * EE + h * DK;
    float* d1 = g_Hc + ((size_t)(b * NN + q0 + row1)) * EE + h * DK;
    #pragma unroll
    for (int nf = 0; nf < 8; nf++) {
        int c = nf * 8 + 2 * t;
        float2 w0 = {oacc[nf][0] * inv0, oacc[nf][1] * inv0};
        float2 w1 = {oacc[nf][2] * inv1, oacc[nf][3] * inv1};
        *(float2*)(d0 + c) = w0;
        *(float2*)(d1 + c) = w1;
    }
}

// ===========================================================================
// Kernel 3: out = Hc @ Wo^T + bo, 3xTF32 mma. grid = (64, 4), 128 threads.
// ===========================================================================
__global__ void __launch_bounds__(128) out_mma_kernel(const float* __restrict__ Wo,
                                                      const float* __restrict__ bo,
                                                      float* __restrict__ out) {
    __shared__ float Xhi[64][36], Xlo[64][36];
    __shared__ float Whi[64][36], Wlo[64][36];

    const int m0 = blockIdx.x * 64;
    const int c0 = blockIdx.y * 64;
    const int tid = threadIdx.x;
    const int wid = tid >> 5;
    const int lane = tid & 31;
    const int g = lane >> 2, t = lane & 3;
    const int row0 = wid * 16 + g, row1 = row0 + 8;

    float c[8][4] = {};

    for (int k0 = 0; k0 < EE; k0 += 32) {
        {   // stage Hc chunk [64 m x 32 k]
            const int xr = tid >> 1, xq = tid & 1;
            const float* src = g_Hc + (size_t)(m0 + xr) * EE + k0 + xq * 16;
            #pragma unroll
            for (int i = 0; i < 4; i++) {
                float4 v = ((const float4*)src)[i];
                int cb = xq * 16 + i * 4;
                hilo(v.x, Xhi[xr][cb + 0], Xlo[xr][cb + 0]);
                hilo(v.y, Xhi[xr][cb + 1], Xlo[xr][cb + 1]);
                hilo(v.z, Xhi[xr][cb + 2], Xlo[xr][cb + 2]);
                hilo(v.w, Xhi[xr][cb + 3], Xlo[xr][cb + 3]);
            }
        }
        {   // stage Wo chunk [64 n x 32 k] (row n = output col, col k)
            const int nr = tid >> 1, nq = tid & 1;
            const float* src = Wo + (size_t)(c0 + nr) * EE + k0 + nq * 16;
            #pragma unroll
            for (int i = 0; i < 4; i++) {
                float4 v = ((const float4*)src)[i];
                int cb = nq * 16 + i * 4;
                hilo(v.x, Whi[nr][cb + 0], Wlo[nr][cb + 0]);
                hilo(v.y, Whi[nr][cb + 1], Wlo[nr][cb + 1]);
                hilo(v.z, Whi[nr][cb + 2], Wlo[nr][cb + 2]);
                hilo(v.w, Whi[nr][cb + 3], Wlo[nr][cb + 3]);
            }
        }
        __syncthreads();

        #pragma unroll
        for (int kc = 0; kc < 4; kc++) {
            uint32_t ahi[4], alo[4];
            ahi[0] = __float_as_uint(Xhi[row0][kc * 8 + t]);
            ahi[1] = __float_as_uint(Xhi[row1][kc * 8 + t]);
            ahi[2] = __float_as_uint(Xhi[row0][kc * 8 + t + 4]);
            ahi[3] = __float_as_uint(Xhi[row1][kc * 8 + t + 4]);
            alo[0] = __float_as_uint(Xlo[row0][kc * 8 + t]);
            alo[1] = __float_as_uint(Xlo[row1][kc * 8 + t]);
            alo[2] = __float_as_uint(Xlo[row0][kc * 8 + t + 4]);
            alo[3] = __float_as_uint(Xlo[row1][kc * 8 + t + 4]);
            #pragma unroll
            for (int nf = 0; nf < 8; nf++) {
                uint32_t bh0 = __float_as_uint(Whi[nf * 8 + g][kc * 8 + t]);
                uint32_t bh1 = __float_as_uint(Whi[nf * 8 + g][kc * 8 + t + 4]);
                uint32_t bl0 = __float_as_uint(Wlo[nf * 8 + g][kc * 8 + t]);
                uint32_t bl1 = __float_as_uint(Wlo[nf * 8 + g][kc * 8 + t + 4]);
                mma_tf32(c[nf], ahi, bh0, bh1);
                mma_tf32(c[nf], ahi, bl0, bl1);
                mma_tf32(c[nf], alo, bh0, bh1);
            }
        }
        __syncthreads();
    }

    #pragma unroll
    for (int nf = 0; nf < 8; nf++) {
        int cc = c0 + nf * 8 + 2 * t;
        float b0v = bo[cc], b1v = bo[cc + 1];
        float2 w0 = {c[nf][0] + b0v, c[nf][1] + b1v};
        float2 w1 = {c[nf][2] + b0v, c[nf][3] + b1v};
        *(float2*)(out + (size_t)(m0 + row0) * EE + cc) = w0;
        *(float2*)(out + (size_t)(m0 + row1) * EE + cc) = w1;
    }
}

extern "C" void kernel_launch(void* const* d_in, const int* in_sizes, int n_in,
                              void* d_out, int out_size) {
    const float* x   = (const float*)d_in[0];
    const int*   adj = (const int*)  d_in[1];
    const float* Wq  = (const float*)d_in[2];
    const float* Wk  = (const float*)d_in[3];
    const float* Wv  = (const float*)d_in[4];
    const float* Wo  = (const float*)d_in[5];
    const float* bo  = (const float*)d_in[6];
    float* out = (float*)d_out;

    qkv_mma_kernel<<<dim3((BB * NN) / 64, 12), 128>>>(x, Wq, Wk, Wv);
    flash_mma_kernel<<<dim3(NN / QM, BB * HH), 256>>>(adj);
    out_mma_kernel<<<dim3((BB * NN) / 64, EE / 64), 128>>>(Wo, bo, out);
}

// round 8
// speedup vs baseline: 2.9928x; 1.4837x over previous
#include <cuda_runtime.h>
#include <cuda_fp16.h>
#include <cstdint>

#define BB 2
#define NN 2048
#define EE 256
#define HH 4
#define DK 64
#define QM 128     // q rows per CTA (flash)
#define BN 64      // keys per tile (flash)

// scratch (no allocations allowed anywhere)
__device__ float    g_Q[BB*HH*NN*DK];   // tf32 bits, pre-scaled by 1/8
__device__ float    g_K[BB*HH*NN*DK];   // tf32 bits
__device__ float    g_V[BB*HH*NN*DK];   // tf32 bits
__device__ float    g_Hc[BB*NN*EE];
__device__ uint32_t g_adjp[BB*NN*(NN/32)];  // packed adjacency bits

__device__ __forceinline__ uint32_t to_tf32(float x) {
    uint32_t u;
    asm("cvt.rna.tf32.f32 %0, %1;" : "=r"(u) : "f"(x));
    return u;
}

__device__ __forceinline__ void mma_tf32(float* c, const uint32_t* a,
                                         uint32_t b0, uint32_t b1) {
    asm volatile(
        "mma.sync.aligned.m16n8k8.row.col.f32.tf32.tf32.f32 "
        "{%0,%1,%2,%3}, {%4,%5,%6,%7}, {%8,%9}, {%0,%1,%2,%3};\n"
        : "+f"(c[0]), "+f"(c[1]), "+f"(c[2]), "+f"(c[3])
        : "r"(a[0]), "r"(a[1]), "r"(a[2]), "r"(a[3]), "r"(b0), "r"(b1));
}

__device__ __forceinline__ void mma_f16(float* c, const uint32_t* a,
                                        uint32_t b0, uint32_t b1) {
    asm volatile(
        "mma.sync.aligned.m16n8k16.row.col.f32.f16.f16.f32 "
        "{%0,%1,%2,%3}, {%4,%5,%6,%7}, {%8,%9}, {%0,%1,%2,%3};\n"
        : "+f"(c[0]), "+f"(c[1]), "+f"(c[2]), "+f"(c[3])
        : "r"(a[0]), "r"(a[1]), "r"(a[2]), "r"(a[3]), "r"(b0), "r"(b1));
}

__device__ __forceinline__ void hilo_h(float v, __half& hi, __half& lo) {
    hi = __float2half_rn(v);
    lo = __float2half_rn(v - __half2float(hi));
}

// ===========================================================================
// Kernel 0: pack adjacency to bitmask. One warp packs 32 consecutive words.
// total words = BB*NN*(NN/32) = 262144; 8 warps/block -> 1024 blocks.
// ===========================================================================
__global__ void pack_adj_kernel(const int* __restrict__ adj) {
    const int lane = threadIdx.x & 31;
    const size_t wbase = (size_t)((blockIdx.x * blockDim.x + threadIdx.x) >> 5) * 32;
    uint32_t mine = 0;
    #pragma unroll
    for (int j = 0; j < 32; j++) {
        int v = adj[(wbase + j) * 32 + lane];
        uint32_t m = __ballot_sync(0xffffffffu, v != 0);
        if (j == lane) mine = m;
    }
    g_adjp[wbase + lane] = mine;
}

// ===========================================================================
// Kernel 1: QKV projection, fp16-split 3xHMMA. grid = (64, 12), 128 threads.
// out[b,h,n,e] = sum_d x[b,n,d] * W[h,d,e]  -> stored as tf32 bits.
// ===========================================================================
__global__ void __launch_bounds__(128) qkv_mma_kernel(const float* __restrict__ x,
                                                      const float* __restrict__ Wq,
                                                      const float* __restrict__ Wk,
                                                      const float* __restrict__ Wv) {
    __shared__ __half Xhi[64][40], Xlo[64][40];
    __shared__ __half Whi[64][40], Wlo[64][40];   // n-major: [e][k]

    const int mat = blockIdx.y >> 2;
    const int h   = blockIdx.y & 3;
    const float* W  = (mat == 0) ? Wq : (mat == 1 ? Wk : Wv);
    float* outp     = (mat == 0) ? g_Q : (mat == 1 ? g_K : g_V);
    const int m0  = blockIdx.x * 64;
    const int tid = threadIdx.x;
    const int wid = tid >> 5;
    const int lane = tid & 31;
    const int g = lane >> 2, t = lane & 3;
    const int row0 = wid * 16 + g, row1 = row0 + 8;

    float c[8][4] = {};

    for (int k0 = 0; k0 < EE; k0 += 32) {
        {   // stage X [64 m x 32 k] as hi/lo halves
            const int xr = tid >> 1, xq = tid & 1;
            const float4* src = (const float4*)(x + (size_t)(m0 + xr) * EE + k0 + xq * 16);
            #pragma unroll
            for (int i = 0; i < 4; i++) {
                float4 v = src[i];
                __half h0, h1, h2, h3, l0, l1, l2, l3;
                hilo_h(v.x, h0, l0); hilo_h(v.y, h1, l1);
                hilo_h(v.z, h2, l2); hilo_h(v.w, h3, l3);
                int cb = xq * 16 + i * 4;
                *(__half2*)(&Xhi[xr][cb])     = __halves2half2(h0, h1);
                *(__half2*)(&Xhi[xr][cb + 2]) = __halves2half2(h2, h3);
                *(__half2*)(&Xlo[xr][cb])     = __halves2half2(l0, l1);
                *(__half2*)(&Xlo[xr][cb + 2]) = __halves2half2(l2, l3);
            }
        }
        {   // stage W [32 k x 64 e] transposed to [e][k] hi/lo halves
            const int n0 = tid & 63, kh = tid >> 6;  // kh in {0,1}
            const float* src = W + (size_t)(h * EE + k0 + kh * 16) * DK + n0;
            #pragma unroll
            for (int j = 0; j < 8; j++) {
                float va = src[(2 * j) * DK];
                float vb = src[(2 * j + 1) * DK];
                __half ha, hb, la, lb;
                hilo_h(va, ha, la); hilo_h(vb, hb, lb);
                *(__half2*)(&Whi[n0][kh * 16 + 2 * j]) = __halves2half2(ha, hb);
                *(__half2*)(&Wlo[n0][kh * 16 + 2 * j]) = __halves2half2(la, lb);
            }
        }
        __syncthreads();

        #pragma unroll
        for (int kc = 0; kc < 32; kc += 16) {
            uint32_t ahi[4], alo[4];
            ahi[0] = *(const uint32_t*)(&Xhi[row0][kc + 2 * t]);
            ahi[1] = *(const uint32_t*)(&Xhi[row1][kc + 2 * t]);
            ahi[2] = *(const uint32_t*)(&Xhi[row0][kc + 8 + 2 * t]);
            ahi[3] = *(const uint32_t*)(&Xhi[row1][kc + 8 + 2 * t]);
            alo[0] = *(const uint32_t*)(&Xlo[row0][kc + 2 * t]);
            alo[1] = *(const uint32_t*)(&Xlo[row1][kc + 2 * t]);
            alo[2] = *(const uint32_t*)(&Xlo[row0][kc + 8 + 2 * t]);
            alo[3] = *(const uint32_t*)(&Xlo[row1][kc + 8 + 2 * t]);
            #pragma unroll
            for (int nf = 0; nf < 8; nf++) {
                uint32_t bh0 = *(const uint32_t*)(&Whi[nf * 8 + g][kc + 2 * t]);
                uint32_t bh1 = *(const uint32_t*)(&Whi[nf * 8 + g][kc + 8 + 2 * t]);
                uint32_t bl0 = *(const uint32_t*)(&Wlo[nf * 8 + g][kc + 2 * t]);
                uint32_t bl1 = *(const uint32_t*)(&Wlo[nf * 8 + g][kc + 8 + 2 * t]);
                mma_f16(c[nf], ahi, bh0, bh1);
                mma_f16(c[nf], ahi, bl0, bl1);
                mma_f16(c[nf], alo, bh0, bh1);
            }
        }
        __syncthreads();
    }

    // epilogue: write tf32 bits to (b,h,n,e) layout; Q pre-scaled by 1/8
    const float sc = (mat == 0) ? 0.125f : 1.0f;
    {
        int m = m0 + row0;
        int b = m >> 11, n = m & (NN - 1);
        float* dst = outp + ((size_t)(b * HH + h) * NN + n) * DK;
        #pragma unroll
        for (int nf = 0; nf < 8; nf++) {
            float2 w = {__uint_as_float(to_tf32(c[nf][0] * sc)),
                        __uint_as_float(to_tf32(c[nf][1] * sc))};
            *(float2*)(dst + nf * 8 + 2 * t) = w;
        }
    }
    {
        int m = m0 + row1;
        int b = m >> 11, n = m & (NN - 1);
        float* dst = outp + ((size_t)(b * HH + h) * NN + n) * DK;
        #pragma unroll
        for (int nf = 0; nf < 8; nf++) {
            float2 w = {__uint_as_float(to_tf32(c[nf][2] * sc)),
                        __uint_as_float(to_tf32(c[nf][3] * sc))};
            *(float2*)(dst + nf * 8 + 2 * t) = w;
        }
    }
}

// ===========================================================================
// Kernel 2: flash attention, mma.sync tf32, 8 warps / 128 q-rows per CTA.
// grid = (16, 8), 256 threads. Q/K/V pre-converted to tf32; adjacency packed.
// ===========================================================================
__global__ void __launch_bounds__(256) flash_mma_kernel() {
    __shared__ float Ks[BN][68];
    __shared__ float Vs[BN][68];
    __shared__ uint32_t adjm[QM][2];

    const int tid = threadIdx.x;
    const int wid = tid >> 5;
    const int lane = tid & 31;
    const int g = lane >> 2;
    const int t = lane & 3;
    const int bh = blockIdx.y;
    const int b  = bh >> 2;
    const int h  = bh & 3;
    const int q0 = blockIdx.x * QM;

    const int row0 = wid * 16 + g;
    const int row1 = row0 + 8;

    // preload Q fragments (already scaled + tf32)
    uint32_t qa[8][4];
    {
        const float* Q0 = g_Q + ((size_t)bh * NN + q0 + row0) * DK;
        const float* Q1 = g_Q + ((size_t)bh * NN + q0 + row1) * DK;
        #pragma unroll
        for (int kc = 0; kc < 8; kc++) {
            qa[kc][0] = __float_as_uint(Q0[kc * 8 + t]);
            qa[kc][1] = __float_as_uint(Q1[kc * 8 + t]);
            qa[kc][2] = __float_as_uint(Q0[kc * 8 + t + 4]);
            qa[kc][3] = __float_as_uint(Q1[kc * 8 + t + 4]);
        }
    }

    float oacc[8][4] = {};
    float m0r = -1e30f, m1r = -1e30f, l0r = 0.f, l1r = 0.f;

    const int krow = tid >> 2, kq = tid & 3;     // K/V staging
    const int arow = tid >> 1, ahalf = tid & 1;  // adj staging

    const uint32_t* adjp_base = g_adjp + ((size_t)b * NN + q0 + arow) * (NN / 32) + ahalf;

    for (int tile = 0; tile < NN / BN; tile++) {
        const int c0 = tile * BN;

        // ---- stage K, V (raw copy, already tf32) + packed adjacency ----
        {
            const float4* Kg = (const float4*)(g_K + ((size_t)bh * NN + c0 + krow) * DK + kq * 16);
            const float4* Vg = (const float4*)(g_V + ((size_t)bh * NN + c0 + krow) * DK + kq * 16);
            #pragma unroll
            for (int i = 0; i < 4; i++) {
                *(float4*)(&Ks[krow][kq * 16 + i * 4]) = Kg[i];
                *(float4*)(&Vs[krow][kq * 16 + i * 4]) = Vg[i];
            }
            adjm[arow][ahalf] = adjp_base[tile * 2];
        }
        __syncthreads();

        // ---- S = Q K^T ----
        float sacc[8][4] = {};
        #pragma unroll
        for (int nf = 0; nf < 8; nf++) {
            #pragma unroll
            for (int kc = 0; kc < 8; kc++) {
                uint32_t b0 = __float_as_uint(Ks[nf * 8 + g][kc * 8 + t]);
                uint32_t b1 = __float_as_uint(Ks[nf * 8 + g][kc * 8 + t + 4]);
                mma_tf32(sacc[nf], qa[kc], b0, b1);
            }
        }

        // ---- masked online softmax ----
        uint32_t w0lo = adjm[row0][0], w0hi = adjm[row0][1];
        uint32_t w1lo = adjm[row1][0], w1hi = adjm[row1][1];
        float mx0 = -1e30f, mx1 = -1e30f;
        #pragma unroll
        for (int nf = 0; nf < 8; nf++) {
            int ca = nf * 8 + 2 * t, cb = ca + 1;
            uint32_t wr0 = (ca < 32) ? w0lo : w0hi;
            uint32_t wr1 = (ca < 32) ? w1lo : w1hi;
            int sa = ca & 31, sb = cb & 31;
            sacc[nf][0] = ((wr0 >> sa) & 1u) ? sacc[nf][0] : -1e38f;
            sacc[nf][1] = ((wr0 >> sb) & 1u) ? sacc[nf][1] : -1e38f;
            sacc[nf][2] = ((wr1 >> sa) & 1u) ? sacc[nf][2] : -1e38f;
            sacc[nf][3] = ((wr1 >> sb) & 1u) ? sacc[nf][3] : -1e38f;
            mx0 = fmaxf(mx0, fmaxf(sacc[nf][0], sacc[nf][1]));
            mx1 = fmaxf(mx1, fmaxf(sacc[nf][2], sacc[nf][3]));
        }
        mx0 = fmaxf(mx0, __shfl_xor_sync(0xffffffffu, mx0, 1));
        mx0 = fmaxf(mx0, __shfl_xor_sync(0xffffffffu, mx0, 2));
        mx1 = fmaxf(mx1, __shfl_xor_sync(0xffffffffu, mx1, 1));
        mx1 = fmaxf(mx1, __shfl_xor_sync(0xffffffffu, mx1, 2));
        float mn0 = fmaxf(m0r, mx0);
        float mn1 = fmaxf(m1r, mx1);
        float s0 = 0.f, s1 = 0.f;
        #pragma unroll
        for (int nf = 0; nf < 8; nf++) {
            float p0 = __expf(sacc[nf][0] - mn0);
            float p1 = __expf(sacc[nf][1] - mn0);
            float p2 = __expf(sacc[nf][2] - mn1);
            float p3 = __expf(sacc[nf][3] - mn1);
            s0 += p0 + p1;
            s1 += p2 + p3;
            sacc[nf][0] = __uint_as_float(to_tf32(p0));
            sacc[nf][1] = __uint_as_float(to_tf32(p1));
            sacc[nf][2] = __uint_as_float(to_tf32(p2));
            sacc[nf][3] = __uint_as_float(to_tf32(p3));
        }
        s0 += __shfl_xor_sync(0xffffffffu, s0, 1);
        s0 += __shfl_xor_sync(0xffffffffu, s0, 2);
        s1 += __shfl_xor_sync(0xffffffffu, s1, 1);
        s1 += __shfl_xor_sync(0xffffffffu, s1, 2);
        float cf0 = __expf(m0r - mn0);
        float cf1 = __expf(m1r - mn1);
        l0r = l0r * cf0 + s0;  m0r = mn0;
        l1r = l1r * cf1 + s1;  m1r = mn1;
        #pragma unroll
        for (int nf = 0; nf < 8; nf++) {
            oacc[nf][0] *= cf0; oacc[nf][1] *= cf0;
            oacc[nf][2] *= cf1; oacc[nf][3] *= cf1;
        }

        // ---- O += P V (P C-layout -> A-layout via quad shuffles) ----
        const int src0 = (lane & ~3) | (t >> 1);
        const int src2 = src0 + 2;
        #pragma unroll
        for (int kc = 0; kc < 8; kc++) {
            float v00 = __shfl_sync(0xffffffffu, sacc[kc][0], src0);
            float v01 = __shfl_sync(0xffffffffu, sacc[kc][1], src0);
            float v10 = __shfl_sync(0xffffffffu, sacc[kc][2], src0);
            float v11 = __shfl_sync(0xffffffffu, sacc[kc][3], src0);
            float v20 = __shfl_sync(0xffffffffu, sacc[kc][0], src2);
            float v21 = __shfl_sync(0xffffffffu, sacc[kc][1], src2);
            float v30 = __shfl_sync(0xffffffffu, sacc[kc][2], src2);
            float v31 = __shfl_sync(0xffffffffu, sacc[kc][3], src2);
            uint32_t pa[4];
            pa[0] = __float_as_uint((t & 1) ? v01 : v00);
            pa[1] = __float_as_uint((t & 1) ? v11 : v10);
            pa[2] = __float_as_uint((t & 1) ? v21 : v20);
            pa[3] = __float_as_uint((t & 1) ? v31 : v30);
            #pragma unroll
            for (int nf = 0; nf < 8; nf++) {
                uint32_t b0 = __float_as_uint(Vs[kc * 8 + t][nf * 8 + g]);
                uint32_t b1 = __float_as_uint(Vs[kc * 8 + t + 4][nf * 8 + g]);
                mma_tf32(oacc[nf], pa, b0, b1);
            }
        }
        __syncthreads();
    }

    // ---- epilogue ----
    float inv0 = (l0r > 0.f) ? 1.f / l0r : 0.f;
    float inv1 = (l1r > 0.f) ? 1.f / l1r : 0.f;
    float* d0 = g_Hc + ((size_t)(b * NN + q0 + row0)) * EE + h * DK;
    float* d1 = g_Hc + ((size_t)(b * NN + q0 + row1)) * EE + h * DK;
    #pragma unroll
    for (int nf = 0; nf < 8; nf++) {
        int c = nf * 8 + 2 * t;
        float2 w0 = {oacc[nf][0] * inv0, oacc[nf][1] * inv0};
        float2 w1 = {oacc[nf][2] * inv1, oacc[nf][3] * inv1};
        *(float2*)(d0 + c) = w0;
        *(float2*)(d1 + c) = w1;
    }
}

// ===========================================================================
// Kernel 3: out = Hc @ Wo^T + bo, fp16-split 3xHMMA. grid = (64, 4), 128 thr.
// ===========================================================================
__global__ void __launch_bounds__(128) out_mma_kernel(const float* __restrict__ Wo,
                                                      const float* __restrict__ bo,
                                                      float* __restrict__ out) {
    __shared__ __half Xhi[64][40], Xlo[64][40];
    __shared__ __half Whi[64][40], Wlo[64][40];   // n-major: [n][k]

    const int m0 = blockIdx.x * 64;
    const int c0 = blockIdx.y * 64;
    const int tid = threadIdx.x;
    const int wid = tid >> 5;
    const int lane = tid & 31;
    const int g = lane >> 2, t = lane & 3;
    const int row0 = wid * 16 + g, row1 = row0 + 8;

    float c[8][4] = {};

    for (int k0 = 0; k0 < EE; k0 += 32) {
        {   // stage Hc [64 m x 32 k]
            const int xr = tid >> 1, xq = tid & 1;
            const float4* src = (const float4*)(g_Hc + (size_t)(m0 + xr) * EE + k0 + xq * 16);
            #pragma unroll
            for (int i = 0; i < 4; i++) {
                float4 v = src[i];
                __half h0, h1, h2, h3, l0, l1, l2, l3;
                hilo_h(v.x, h0, l0); hilo_h(v.y, h1, l1);
                hilo_h(v.z, h2, l2); hilo_h(v.w, h3, l3);
                int cb = xq * 16 + i * 4;
                *(__half2*)(&Xhi[xr][cb])     = __halves2half2(h0, h1);
                *(__half2*)(&Xhi[xr][cb + 2]) = __halves2half2(h2, h3);
                *(__half2*)(&Xlo[xr][cb])     = __halves2half2(l0, l1);
                *(__half2*)(&Xlo[xr][cb + 2]) = __halves2half2(l2, l3);
            }
        }
        {   // stage Wo [64 n x 32 k] (rows of Wo are n, contiguous in k)
            const int nr = tid >> 1, nq = tid & 1;
            const float4* src = (const float4*)(Wo + (size_t)(c0 + nr) * EE + k0 + nq * 16);
            #pragma unroll
            for (int i = 0; i < 4; i++) {
                float4 v = src[i];
                __half h0, h1, h2, h3, l0, l1, l2, l3;
                hilo_h(v.x, h0, l0); hilo_h(v.y, h1, l1);
                hilo_h(v.z, h2, l2); hilo_h(v.w, h3, l3);
                int cb = nq * 16 + i * 4;
                *(__half2*)(&Whi[nr][cb])     = __halves2half2(h0, h1);
                *(__half2*)(&Whi[nr][cb + 2]) = __halves2half2(h2, h3);
                *(__half2*)(&Wlo[nr][cb])     = __halves2half2(l0, l1);
                *(__half2*)(&Wlo[nr][cb + 2]) = __halves2half2(l2, l3);
            }
        }
        __syncthreads();

        #pragma unroll
        for (int kc = 0; kc < 32; kc += 16) {
            uint32_t ahi[4], alo[4];
            ahi[0] = *(const uint32_t*)(&Xhi[row0][kc + 2 * t]);
            ahi[1] = *(const uint32_t*)(&Xhi[row1][kc + 2 * t]);
            ahi[2] = *(const uint32_t*)(&Xhi[row0][kc + 8 + 2 * t]);
            ahi[3] = *(const uint32_t*)(&Xhi[row1][kc + 8 + 2 * t]);
            alo[0] = *(const uint32_t*)(&Xlo[row0][kc + 2 * t]);
            alo[1] = *(const uint32_t*)(&Xlo[row1][kc + 2 * t]);
            alo[2] = *(const uint32_t*)(&Xlo[row0][kc + 8 + 2 * t]);
            alo[3] = *(const uint32_t*)(&Xlo[row1][kc + 8 + 2 * t]);
            #pragma unroll
            for (int nf = 0; nf < 8; nf++) {
                uint32_t bh0 = *(const uint32_t*)(&Whi[nf * 8 + g][kc + 2 * t]);
                uint32_t bh1 = *(const uint32_t*)(&Whi[nf * 8 + g][kc + 8 + 2 * t]);
                uint32_t bl0 = *(const uint32_t*)(&Wlo[nf * 8 + g][kc + 2 * t]);
                uint32_t bl1 = *(const uint32_t*)(&Wlo[nf * 8 + g][kc + 8 + 2 * t]);
                mma_f16(c[nf], ahi, bh0, bh1);
                mma_f16(c[nf], ahi, bl0, bl1);
                mma_f16(c[nf], alo, bh0, bh1);
            }
        }
        __syncthreads();
    }

    #pragma unroll
    for (int nf = 0; nf < 8; nf++) {
        int cc = c0 + nf * 8 + 2 * t;
        float b0v = bo[cc], b1v = bo[cc + 1];
        float2 w0 = {c[nf][0] + b0v, c[nf][1] + b1v};
        float2 w1 = {c[nf][2] + b0v, c[nf][3] + b1v};
        *(float2*)(out + (size_t)(m0 + row0) * EE + cc) = w0;
        *(float2*)(out + (size_t)(m0 + row1) * EE + cc) = w1;
    }
}

extern "C" void kernel_launch(void* const* d_in, const int* in_sizes, int n_in,
                              void* d_out, int out_size) {
    const float* x   = (const float*)d_in[0];
    const int*   adj = (const int*)  d_in[1];
    const float* Wq  = (const float*)d_in[2];
    const float* Wk  = (const float*)d_in[3];
    const float* Wv  = (const float*)d_in[4];
    const float* Wo  = (const float*)d_in[5];
    const float* bo  = (const float*)d_in[6];
    float* out = (float*)d_out;

    // 8 warps per 256-thread block, each warp packs 32 words
    pack_adj_kernel<<<(BB * NN * (NN / 32)) / (8 * 32), 256>>>(adj);
    qkv_mma_kernel<<<dim3((BB * NN) / 64, 12), 128>>>(x, Wq, Wk, Wv);
    flash_mma_kernel<<<dim3(NN / QM, BB * HH), 256>>>();
    out_mma_kernel<<<dim3((BB * NN) / 64, EE / 64), 128>>>(Wo, bo, out);
}